// round 8
// baseline (speedup 1.0000x reference)
#include <cuda_runtime.h>
#include <math.h>

// Problem constants
#define BB 2048     // batch (samples == queries)
#define RR 64       // receptors
#define TILES 16    // BB / 128
#define NPAIRS 136  // TILES*(TILES+1)/2
#define QT 16       // query tiles for logsum
#define CB 128      // row-chunks for covariance Gram
#define CROWS 16    // rows per covariance chunk (CB*CROWS == BB)
#define GRB 32      // gram-reduce blocks (32 x 128 threads = 4096 cells)
#define SKIP_GAP 4.0f  // scaled-unit gap => all args <= -16, exp < 1.2e-7

// -------- device scratch (static: no allocations allowed) --------
__device__ float g_scaled[RR * BB];        // column-major SORTED scaled values
__device__ float g_dnorm[RR];              // invh / (B * sqrt(2*pi))
__device__ float g_mean[RR];
__device__ float g_part[TILES * RR * BB];  // [slot][r][q] density partial sums (8MB)
__device__ float g_ent_partial[QT * RR];   // per-(qtile, r) sum of log(density+eps)
__device__ float g_gram[CB * RR * RR];     // RAW (uncentered) Gram partials (2MB)
__device__ float g_cov_partial[GRB];       // per-block sum of squared off-diag cov

// Hardware exp2: single MUFU.EX2 (ftz on tiny results — harmless here).
__device__ __forceinline__ float ex2(float x) {
    float y;
    asm("ex2.approx.ftz.f32 %0, %1;" : "=f"(y) : "f"(x));
    return y;
}

// ---------------------------------------------------------------------------
// Stage 1 (fused, 512 threads):
//   blocks [0, RR)      -> per-column stats + scale + bitonic SORT + store
//   blocks [RR, RR+CB)  -> raw Gram partial over 16 rows (first 256 threads)
// Sorting a column is safe: entropy is a mean over queries (order-invariant),
// and downstream per-query ops (log, scale) are elementwise.
// ---------------------------------------------------------------------------
__global__ void stats_cov_kernel(const float* __restrict__ act) {
    const int tid = threadIdx.x;   // 512 threads

    if (blockIdx.x < RR) {
        // ---------------- stats + sort half ----------------
        __shared__ float sh[BB];
        __shared__ float red[512];
        const int r = blockIdx.x;

        float s = 0.f;
        #pragma unroll
        for (int i = tid; i < BB; i += 512) {
            float v = act[i * RR + r];
            sh[i] = v;
            s += v;
        }
        red[tid] = s;
        __syncthreads();
        for (int o = 256; o > 0; o >>= 1) {
            if (tid < o) red[tid] += red[tid + o];
            __syncthreads();
        }
        const float mean = red[0] * (1.0f / BB);
        __syncthreads();

        float ss = 0.f;
        #pragma unroll
        for (int i = tid; i < BB; i += 512) {
            float d = sh[i] - mean;
            ss += d * d;
        }
        red[tid] = ss;
        __syncthreads();
        for (int o = 256; o > 0; o >>= 1) {
            if (tid < o) red[tid] += red[tid + o];
            __syncthreads();
        }
        const float var  = red[0] * (1.0f / (BB - 1));
        const float stdv = sqrtf(var);
        // BANDWIDTH_FACTOR * std * B^(-0.2);  2048^(-0.2) = 0.21763764
        const float h    = fmaxf(1.06f * stdv * 0.21763764f, 1e-4f);
        const float invh = 1.0f / h;

        // sqrt(0.5 * log2(e)) so exp(-0.5*u^2) == 2^{-(u')^2}
        const float KS = 0.84932184f;
        const float k  = invh * KS;

        __syncthreads();
        // scale in place
        #pragma unroll
        for (int i = tid; i < BB; i += 512) sh[i] *= k;
        __syncthreads();

        // bitonic sort of 2048 elements, 512 threads (2 pairs/thread/stage)
        for (unsigned kk = 2; kk <= BB; kk <<= 1) {
            for (unsigned j = kk >> 1; j > 0; j >>= 1) {
                #pragma unroll 2
                for (unsigned m = tid; m < BB / 2; m += 512) {
                    const unsigned i = 2u * m - (m & (j - 1u));
                    const unsigned p = i + j;
                    const bool up = ((i & kk) == 0u);
                    const float a = sh[i];
                    const float b = sh[p];
                    if ((a > b) == up) { sh[i] = b; sh[p] = a; }
                }
                __syncthreads();
            }
        }

        #pragma unroll
        for (int i = tid; i < BB; i += 512)
            g_scaled[r * BB + i] = sh[i];

        if (tid == 0) {
            g_dnorm[r] = invh * (1.0f / (2048.0f * 2.5066282746310002f));
            g_mean[r]  = mean;
        }
    } else {
        // ---------------- raw Gram half (256 active threads) ----------------
        __shared__ float ch[CROWS * RR];   // 16 x 64 raw rows (4KB)
        const int b = blockIdx.x - RR;     // 0..CB-1

        // coalesced load: 512 threads x 1 float2 = 1024 floats
        reinterpret_cast<float2*>(ch)[tid] =
            reinterpret_cast<const float2*>(act + b * CROWS * RR)[tid];
        __syncthreads();
        if (tid >= 256) return;

        const int ti = tid & 15;   // column-group i
        const int tj = tid >> 4;   // column-group j
        float acc[4][4];
        #pragma unroll
        for (int y = 0; y < 4; ++y)
            #pragma unroll
            for (int x = 0; x < 4; ++x) acc[y][x] = 0.f;

        const float4* __restrict__ s4 = reinterpret_cast<const float4*>(ch);
        #pragma unroll
        for (int s = 0; s < CROWS; ++s) {
            const float4 ai = s4[s * 16 + ti];
            const float4 aj = s4[s * 16 + tj];
            const float av[4] = { ai.x, ai.y, ai.z, ai.w };
            const float bv[4] = { aj.x, aj.y, aj.z, aj.w };
            #pragma unroll
            for (int y = 0; y < 4; ++y)
                #pragma unroll
                for (int x = 0; x < 4; ++x)
                    acc[y][x] += av[x] * bv[y];
        }

        float* __restrict__ gp = g_gram + b * RR * RR;
        #pragma unroll
        for (int y = 0; y < 4; ++y)
            #pragma unroll
            for (int x = 0; x < 4; ++x)
                gp[(tj * 4 + y) * RR + (ti * 4 + x)] = acc[y][x];
    }
}

// ---------------------------------------------------------------------------
// Stage 2: symmetric KDE on SORTED columns with distance culling.
// Block = (tile-pair p, receptor r), 128 threads. If the value gap between
// tile I's max and tile J's min is >= SKIP_GAP, every kernel value is
// < 1.2e-7 -> write zeros and exit (deterministic, error ~1e-6 relative).
// Otherwise: lane owns 4 tile-J columns in registers; (query, row-acc)
// rotates across the 32 lanes via SHFL; each exp serves both densities.
// ---------------------------------------------------------------------------
__global__ void kde_sym_kernel() {
    const int r = blockIdx.y;
    // map linear pair index -> (I, J), I <= J
    int I = 0, rem = blockIdx.x;
    while (rem >= TILES - I) { rem -= TILES - I; ++I; }
    const int J = I + rem;

    const int tid  = threadIdx.x;   // 128
    const int lane = tid & 31;
    const int w    = tid >> 5;

    const float* __restrict__ col = g_scaled + r * BB;

    // sorted => tile bounds are the end elements
    const float hiI = col[I * 128 + 127];
    const float loJ = col[J * 128];
    if (loJ - hiI >= SKIP_GAP) {
        // negligible contribution: zero both slots (I < J here; diag gap <= 0)
        g_part[I * (RR * BB) + r * BB + J * 128 + tid] = 0.f;
        g_part[J * (RR * BB) + r * BB + I * 128 + tid] = 0.f;
        return;
    }

    const float4 sv = reinterpret_cast<const float4*>(col + J * 128)[lane];
    float aqc  = col[I * 128 + tid];
    float rowc = 0.f;
    float4 ca  = make_float4(0.f, 0.f, 0.f, 0.f);

    const unsigned FULL = 0xFFFFFFFFu;

    if (I != J) {
        #pragma unroll 8
        for (int m = 0; m < 32; ++m) {
            float u, v0, v1, v2, v3;
            u = aqc - sv.x; v0 = ex2(-u * u);
            u = aqc - sv.y; v1 = ex2(-u * u);
            u = aqc - sv.z; v2 = ex2(-u * u);
            u = aqc - sv.w; v3 = ex2(-u * u);
            ca.x += v0; ca.y += v1; ca.z += v2; ca.w += v3;
            rowc += (v0 + v1) + (v2 + v3);
            aqc  = __shfl_sync(FULL, aqc,  (lane + 1) & 31);
            rowc = __shfl_sync(FULL, rowc, (lane + 1) & 31);
        }

        __shared__ float shc[4][128];
        reinterpret_cast<float4*>(shc[w])[lane] = ca;
        __syncthreads();
        const float ct = shc[0][tid] + shc[1][tid] + shc[2][tid] + shc[3][tid];

        g_part[I * (RR * BB) + r * BB + J * 128 + tid] = ct;    // tile-J densities
        g_part[J * (RR * BB) + r * BB + I * 128 + tid] = rowc;  // tile-I densities
    } else {
        #pragma unroll 8
        for (int m = 0; m < 32; ++m) {
            float u, v0, v1, v2, v3;
            u = aqc - sv.x; v0 = ex2(-u * u);
            u = aqc - sv.y; v1 = ex2(-u * u);
            u = aqc - sv.z; v2 = ex2(-u * u);
            u = aqc - sv.w; v3 = ex2(-u * u);
            rowc += (v0 + v1) + (v2 + v3);
            aqc  = __shfl_sync(FULL, aqc,  (lane + 1) & 31);
            rowc = __shfl_sync(FULL, rowc, (lane + 1) & 31);
        }
        g_part[I * (RR * BB) + r * BB + I * 128 + tid] = rowc;
    }
}

// ---------------------------------------------------------------------------
// Stage 3 (fused): blocks [0, QT*RR)            -> logsum of densities
//                  blocks [QT*RR, QT*RR + GRB)  -> Gram fold + mean-correct +
//                                                  off-diag square-sum
// ---------------------------------------------------------------------------
__global__ void reduce_kernel() {
    __shared__ float red[128];
    const int tid = threadIdx.x;   // 128

    if (blockIdx.x < QT * RR) {
        // ---------------- logsum half ----------------
        const int r  = blockIdx.x >> 4;
        const int qt = blockIdx.x & 15;
        const int q  = qt * 128 + tid;

        float s = 0.f;
        #pragma unroll
        for (int slot = 0; slot < TILES; ++slot)
            s += g_part[slot * (RR * BB) + r * BB + q];

        const float dens = s * g_dnorm[r];
        red[tid] = logf(dens + 1e-8f);
        __syncthreads();
        for (int o = 64; o > 0; o >>= 1) {
            if (tid < o) red[tid] += red[tid + o];
            __syncthreads();
        }
        if (tid == 0) g_ent_partial[qt * RR + r] = red[0];
    } else {
        // ---------------- Gram-reduce half ----------------
        const int gb = blockIdx.x - QT * RR;   // 0..GRB-1
        const int p  = gb * 128 + tid;         // cell in 64x64
        const int i  = p & (RR - 1);
        const int j  = p >> 6;

        float g = 0.f;
        #pragma unroll 16
        for (int b = 0; b < CB; ++b) g += g_gram[b * RR * RR + p];

        // centered Gram: sum((x_i - m_i)(x_j - m_j)) = raw - B*m_i*m_j
        g -= (float)BB * g_mean[i] * g_mean[j];

        float cs = 0.f;
        if (i != j) {
            const float c = g * (1.0f / (BB - 1));
            cs = c * c;
        }
        red[tid] = cs;
        __syncthreads();
        for (int o = 64; o > 0; o >>= 1) {
            if (tid < o) red[tid] += red[tid + o];
            __syncthreads();
        }
        if (tid == 0) g_cov_partial[gb] = red[0];
    }
}

// ---------------------------------------------------------------------------
// Stage 4: deterministic final combine (tiny: 1024 + 32 floats).
// ---------------------------------------------------------------------------
__global__ void final_kernel(float* __restrict__ out) {
    __shared__ float red[256];
    const int tid = threadIdx.x;  // 256 threads

    // 1024 entropy partials as 256 float4 loads (MLP-friendly)
    const float4 e4 = reinterpret_cast<const float4*>(g_ent_partial)[tid];
    float es = (e4.x + e4.y) + (e4.z + e4.w);

    float cs = 0.f;
    if (tid < GRB) cs = g_cov_partial[tid];

    red[tid] = es * (1.0f / (float)(BB * RR)) + cs;
    __syncthreads();
    for (int o = 128; o > 0; o >>= 1) {
        if (tid < o) red[tid] += red[tid + o];
        __syncthreads();
    }
    if (tid == 0) out[0] = red[0];
}

// ---------------------------------------------------------------------------
extern "C" void kernel_launch(void* const* d_in, const int* in_sizes, int n_in,
                              void* d_out, int out_size) {
    const float* act = (const float*)d_in[0];
    float* out = (float*)d_out;
    (void)in_sizes; (void)n_in; (void)out_size;

    stats_cov_kernel<<<RR + CB, 512>>>(act);
    kde_sym_kernel<<<dim3(NPAIRS, RR), 128>>>();
    reduce_kernel<<<QT * RR + GRB, 128>>>();
    final_kernel<<<1, 256>>>(out);
}

// round 10
// speedup vs baseline: 1.0099x; 1.0099x over previous
#include <cuda_runtime.h>
#include <math.h>

// Problem constants
#define BB 2048     // batch (samples == queries)
#define RR 64       // receptors
#define TILES 16    // BB / 128
#define NPAIRS 136  // TILES*(TILES+1)/2
#define QT 16       // query tiles for logsum
#define CB 128      // row-chunks for covariance Gram
#define CROWS 16    // rows per covariance chunk (CB*CROWS == BB)
#define GRB 32      // gram-reduce blocks (32 x 128 threads = 4096 cells)
#define RED_BLOCKS (QT * RR + GRB)   // 1056

// -------- device scratch (static: no allocations allowed) --------
__device__ float g_scaled[RR * BB];        // column-major, value * invh * sqrt(0.5*log2e)
__device__ float g_dnorm[RR];              // invh / (B * sqrt(2*pi))
__device__ float g_mean[RR];
__device__ float g_part[TILES * RR * BB];  // [slot][r][q] density partial sums (8MB)
__device__ float g_ent_partial[QT * RR];   // per-(qtile, r) sum of log(density+eps)
__device__ float g_gram[CB * RR * RR];     // RAW (uncentered) Gram partials (2MB)
__device__ float g_cov_partial[GRB];       // per-block sum of squared off-diag cov
__device__ unsigned int g_sem;             // last-block-done ticket counter

// Hardware exp2: single MUFU.EX2 (ftz on tiny results — harmless here).
__device__ __forceinline__ float ex2(float x) {
    float y;
    asm("ex2.approx.ftz.f32 %0, %1;" : "=f"(y) : "f"(x));
    return y;
}

// ---------------------------------------------------------------------------
// Stage 1 (fused): blocks [0, RR)      -> per-column stats + scaled copy
//                  blocks [RR, RR+CB)  -> raw Gram partial over 16 rows
// Block 0 also resets the reduce-stage ticket counter (stream order
// guarantees this happens before any reduce block increments it).
// ---------------------------------------------------------------------------
__global__ void stats_cov_kernel(const float* __restrict__ act) {
    const int tid = threadIdx.x;   // 256 threads

    if (blockIdx.x == 0 && tid == 0) g_sem = 0u;

    if (blockIdx.x < RR) {
        // ---------------- stats half ----------------
        __shared__ float sh[BB];
        __shared__ float red[256];
        const int r = blockIdx.x;

        float s = 0.f;
        #pragma unroll
        for (int i = tid; i < BB; i += 256) {
            float v = act[i * RR + r];
            sh[i] = v;
            s += v;
        }
        red[tid] = s;
        __syncthreads();
        for (int o = 128; o > 0; o >>= 1) {
            if (tid < o) red[tid] += red[tid + o];
            __syncthreads();
        }
        const float mean = red[0] * (1.0f / BB);
        __syncthreads();

        float ss = 0.f;
        #pragma unroll
        for (int i = tid; i < BB; i += 256) {
            float d = sh[i] - mean;
            ss += d * d;
        }
        red[tid] = ss;
        __syncthreads();
        for (int o = 128; o > 0; o >>= 1) {
            if (tid < o) red[tid] += red[tid + o];
            __syncthreads();
        }
        const float var  = red[0] * (1.0f / (BB - 1));
        const float stdv = sqrtf(var);
        // BANDWIDTH_FACTOR * std * B^(-0.2);  2048^(-0.2) = 0.21763764
        const float h    = fmaxf(1.06f * stdv * 0.21763764f, 1e-4f);
        const float invh = 1.0f / h;

        // sqrt(0.5 * log2(e)) so exp(-0.5*u^2) == 2^{-(u')^2}
        const float KS = 0.84932184f;
        const float k  = invh * KS;
        #pragma unroll
        for (int i = tid; i < BB; i += 256)
            g_scaled[r * BB + i] = sh[i] * k;

        if (tid == 0) {
            g_dnorm[r] = invh * (1.0f / (2048.0f * 2.5066282746310002f));
            g_mean[r]  = mean;
        }
    } else {
        // ---------------- raw Gram half ----------------
        __shared__ float ch[CROWS * RR];   // 16 x 64 raw rows (4KB)
        const int b = blockIdx.x - RR;     // 0..CB-1

        // coalesced float4 load: 256 threads x 1 float4 = 1024 floats
        reinterpret_cast<float4*>(ch)[tid] =
            reinterpret_cast<const float4*>(act + b * CROWS * RR)[tid];
        __syncthreads();

        const int ti = tid & 15;   // column-group i
        const int tj = tid >> 4;   // column-group j
        float acc[4][4];
        #pragma unroll
        for (int y = 0; y < 4; ++y)
            #pragma unroll
            for (int x = 0; x < 4; ++x) acc[y][x] = 0.f;

        const float4* __restrict__ s4 = reinterpret_cast<const float4*>(ch);
        #pragma unroll
        for (int s = 0; s < CROWS; ++s) {
            const float4 ai = s4[s * 16 + ti];
            const float4 aj = s4[s * 16 + tj];
            const float av[4] = { ai.x, ai.y, ai.z, ai.w };
            const float bv[4] = { aj.x, aj.y, aj.z, aj.w };
            #pragma unroll
            for (int y = 0; y < 4; ++y)
                #pragma unroll
                for (int x = 0; x < 4; ++x)
                    acc[y][x] += av[x] * bv[y];
        }

        float* __restrict__ gp = g_gram + b * RR * RR;
        #pragma unroll
        for (int y = 0; y < 4; ++y)
            #pragma unroll
            for (int x = 0; x < 4; ++x)
                gp[(tj * 4 + y) * RR + (ti * 4 + x)] = acc[y][x];
    }
}

// ---------------------------------------------------------------------------
// Stage 2: symmetric KDE. Block = (tile-pair p, receptor r), 128 threads.
// Each lane owns 4 columns of tile J in registers; (query, row accumulator)
// rotates across the 32 lanes via SHFL. Off-diagonal pairs: each exp serves
// both a row (tile-I) and a column (tile-J) density. No atomics; every
// g_part cell is written by exactly one block.
// ---------------------------------------------------------------------------
__global__ void kde_sym_kernel() {
    const int r = blockIdx.y;
    // map linear pair index -> (I, J), I <= J
    int I = 0, rem = blockIdx.x;
    while (rem >= TILES - I) { rem -= TILES - I; ++I; }
    const int J = I + rem;

    const int tid  = threadIdx.x;   // 128
    const int lane = tid & 31;
    const int w    = tid >> 5;

    const float* __restrict__ col = g_scaled + r * BB;

    const float4 sv = reinterpret_cast<const float4*>(col + J * 128)[lane];
    float aqc  = col[I * 128 + tid];
    float rowc = 0.f;
    float4 ca  = make_float4(0.f, 0.f, 0.f, 0.f);

    const unsigned FULL = 0xFFFFFFFFu;

    if (I != J) {
        #pragma unroll 8
        for (int m = 0; m < 32; ++m) {
            float u, v0, v1, v2, v3;
            u = aqc - sv.x; v0 = ex2(-u * u);
            u = aqc - sv.y; v1 = ex2(-u * u);
            u = aqc - sv.z; v2 = ex2(-u * u);
            u = aqc - sv.w; v3 = ex2(-u * u);
            ca.x += v0; ca.y += v1; ca.z += v2; ca.w += v3;
            rowc += (v0 + v1) + (v2 + v3);
            aqc  = __shfl_sync(FULL, aqc,  (lane + 1) & 31);
            rowc = __shfl_sync(FULL, rowc, (lane + 1) & 31);
        }

        __shared__ float shc[4][128];
        reinterpret_cast<float4*>(shc[w])[lane] = ca;
        __syncthreads();
        const float ct = shc[0][tid] + shc[1][tid] + shc[2][tid] + shc[3][tid];

        g_part[I * (RR * BB) + r * BB + J * 128 + tid] = ct;    // tile-J densities
        g_part[J * (RR * BB) + r * BB + I * 128 + tid] = rowc;  // tile-I densities
    } else {
        #pragma unroll 8
        for (int m = 0; m < 32; ++m) {
            float u, v0, v1, v2, v3;
            u = aqc - sv.x; v0 = ex2(-u * u);
            u = aqc - sv.y; v1 = ex2(-u * u);
            u = aqc - sv.z; v2 = ex2(-u * u);
            u = aqc - sv.w; v3 = ex2(-u * u);
            rowc += (v0 + v1) + (v2 + v3);
            aqc  = __shfl_sync(FULL, aqc,  (lane + 1) & 31);
            rowc = __shfl_sync(FULL, rowc, (lane + 1) & 31);
        }
        g_part[I * (RR * BB) + r * BB + I * 128 + tid] = rowc;
    }
}

// ---------------------------------------------------------------------------
// Stage 3 (fused): blocks [0, QT*RR)            -> logsum of densities
//                  blocks [QT*RR, QT*RR + GRB)  -> Gram fold + mean-correct +
//                                                  off-diag square-sum
// The LAST block to finish (atomic ticket) performs the final combine and
// writes out[0]. Combine reads fixed addresses in fixed order -> the result
// is bitwise deterministic regardless of which block draws the last ticket.
// No spin-waits: every block either exits or combines. Cannot deadlock.
// ---------------------------------------------------------------------------
__global__ void reduce_kernel(float* __restrict__ out) {
    __shared__ float red[128];
    __shared__ unsigned int s_ticket;
    const int tid = threadIdx.x;   // 128

    if (blockIdx.x < QT * RR) {
        // ---------------- logsum half ----------------
        const int r  = blockIdx.x >> 4;
        const int qt = blockIdx.x & 15;
        const int q  = qt * 128 + tid;

        float s = 0.f;
        #pragma unroll
        for (int slot = 0; slot < TILES; ++slot)
            s += g_part[slot * (RR * BB) + r * BB + q];

        const float dens = s * g_dnorm[r];
        red[tid] = logf(dens + 1e-8f);
        __syncthreads();
        for (int o = 64; o > 0; o >>= 1) {
            if (tid < o) red[tid] += red[tid + o];
            __syncthreads();
        }
        if (tid == 0) g_ent_partial[qt * RR + r] = red[0];
    } else {
        // ---------------- Gram-reduce half ----------------
        const int gb = blockIdx.x - QT * RR;   // 0..GRB-1
        const int p  = gb * 128 + tid;         // cell in 64x64
        const int i  = p & (RR - 1);
        const int j  = p >> 6;

        float g = 0.f;
        #pragma unroll 16
        for (int b = 0; b < CB; ++b) g += g_gram[b * RR * RR + p];

        // centered Gram: sum((x_i - m_i)(x_j - m_j)) = raw - B*m_i*m_j
        g -= (float)BB * g_mean[i] * g_mean[j];

        float cs = 0.f;
        if (i != j) {
            const float c = g * (1.0f / (BB - 1));
            cs = c * c;
        }
        red[tid] = cs;
        __syncthreads();
        for (int o = 64; o > 0; o >>= 1) {
            if (tid < o) red[tid] += red[tid + o];
            __syncthreads();
        }
        if (tid == 0) g_cov_partial[gb] = red[0];
    }

    // ---- last-block-done final combine ----
    __threadfence();                 // make this block's partial visible
    __syncthreads();
    if (tid == 0) s_ticket = atomicAdd(&g_sem, 1u);
    __syncthreads();
    if (s_ticket != RED_BLOCKS - 1) return;

    __threadfence();                 // acquire: see all other partials

    // 1024 entropy partials: 128 threads x 2 float4 loads
    const float4 e0 = reinterpret_cast<const float4*>(g_ent_partial)[tid];
    const float4 e1 = reinterpret_cast<const float4*>(g_ent_partial)[tid + 128];
    float es = ((e0.x + e0.y) + (e0.z + e0.w)) + ((e1.x + e1.y) + (e1.z + e1.w));

    float cs = 0.f;
    if (tid < GRB) cs = g_cov_partial[tid];

    __syncthreads();                 // red[] reuse
    red[tid] = es * (1.0f / (float)(BB * RR)) + cs;
    __syncthreads();
    for (int o = 64; o > 0; o >>= 1) {
        if (tid < o) red[tid] += red[tid + o];
        __syncthreads();
    }
    if (tid == 0) out[0] = red[0];
}

// ---------------------------------------------------------------------------
extern "C" void kernel_launch(void* const* d_in, const int* in_sizes, int n_in,
                              void* d_out, int out_size) {
    const float* act = (const float*)d_in[0];
    float* out = (float*)d_out;
    (void)in_sizes; (void)n_in; (void)out_size;

    stats_cov_kernel<<<RR + CB, 256>>>(act);
    kde_sym_kernel<<<dim3(NPAIRS, RR), 128>>>();
    reduce_kernel<<<RED_BLOCKS, 128>>>(out);
}